// round 2
// baseline (speedup 1.0000x reference)
#include <cuda_runtime.h>
#include <math.h>

#define NN 1024
#define DNF 128
#define G3 384

// ---------------- device scratch (static allocation only) ----------------
__device__ float g_er [NN * DNF];        // adj-weighted e reduction
__device__ float g_ce [NN * DNF];        // er @ w_msg_e^T   (layer-invariant)
__device__ float g_big[NN * 512];        // [hm | gh]  = h @ [w_msg_h; w_hh]^T
__device__ float g_m  [NN * DNF];        // messages
__device__ float g_h  [NN * DNF];        // current node state
__device__ float g_gi [NN * G3];         // gi gates; reused: gate_pre / out_pre
__device__ float g_wcat[512 * DNF];      // [w_msg_h ; w_hh] concat
__device__ int   g_nzi[NN * NN];
__device__ float g_nzv[NN * NN];
__device__ int   g_nzc[NN];
__device__ float g_part[64 * DNF];

// ---------------- f32x2 helpers -------------------------------------------
__device__ __forceinline__ unsigned long long dup2(float x) {
    unsigned int v = __float_as_uint(x);
    unsigned long long r;
    asm("mov.b64 %0, {%1, %1};" : "=l"(r) : "r"(v));
    return r;
}
__device__ __forceinline__ void fma2(unsigned long long& d,
                                     unsigned long long a,
                                     unsigned long long b) {
    asm("fma.rn.f32x2 %0, %1, %2, %0;" : "+l"(d) : "l"(a), "l"(b));
}
__device__ __forceinline__ void unpack2(unsigned long long v, float& lo, float& hi) {
    unsigned int a, b;
    asm("mov.b64 {%0, %1}, %2;" : "=r"(a), "=r"(b) : "l"(v));
    lo = __uint_as_float(a); hi = __uint_as_float(b);
}

// ---------------------------------------------------------------------------
// Kernel 1: adjacency compaction + adj-weighted reduction of e
// ---------------------------------------------------------------------------
__global__ void k_build_ereduce(const float* __restrict__ adj,
                                const float* __restrict__ e) {
    const int i    = blockIdx.x;
    const int tid  = threadIdx.x;       // 256
    const int lane = tid & 31;
    const int w    = tid >> 5;          // 8 warps

    __shared__ int   s_idx[NN];
    __shared__ float s_val[NN];
    __shared__ int   s_wcnt[8];
    __shared__ int   s_woff[8];
    __shared__ int   s_cnt;
    __shared__ float s_red[8 * DNF];

    const float* arow = adj + (size_t)i * NN;
    const int base = w * 128;

    float av[4]; unsigned mm[4];
#pragma unroll
    for (int c = 0; c < 4; c++) av[c] = arow[base + c * 32 + lane];
    int tot = 0;
#pragma unroll
    for (int c = 0; c < 4; c++) {
        mm[c] = __ballot_sync(0xffffffffu, av[c] != 0.0f);
        tot += __popc(mm[c]);
    }
    if (lane == 0) s_wcnt[w] = tot;
    __syncthreads();
    if (tid == 0) {
        int run = 0;
        for (int ww = 0; ww < 8; ww++) { s_woff[ww] = run; run += s_wcnt[ww]; }
        s_cnt = run;
    }
    __syncthreads();

    int off = s_woff[w];
    const unsigned lm = (1u << lane) - 1u;
#pragma unroll
    for (int c = 0; c < 4; c++) {
        if (av[c] != 0.0f) {
            int p = off + __popc(mm[c] & lm);
            s_idx[p] = base + c * 32 + lane;
            s_val[p] = av[c];
        }
        off += __popc(mm[c]);
    }
    __syncthreads();

    const int cnt = s_cnt;
    if (tid == 0) g_nzc[i] = cnt;
    for (int k = tid; k < cnt; k += 256) {
        g_nzi[(size_t)i * NN + k] = s_idx[k];
        g_nzv[(size_t)i * NN + k] = s_val[k];
    }

    // adj-weighted gather-reduce of e: 8 groups x 32 lanes, float4 per lane
    const int q = tid & 31;             // float4 index over 128 features
    const int g = tid >> 5;             // group
    const float* ebase = e + (size_t)i * NN * DNF;
    float4 acc = make_float4(0.f, 0.f, 0.f, 0.f);
    for (int k = g; k < cnt; k += 8) {
        float v = s_val[k];
        float4 ev = *(const float4*)(ebase + (size_t)s_idx[k] * DNF + q * 4);
        acc.x += v * ev.x; acc.y += v * ev.y;
        acc.z += v * ev.z; acc.w += v * ev.w;
    }
    s_red[g * DNF + q * 4 + 0] = acc.x;
    s_red[g * DNF + q * 4 + 1] = acc.y;
    s_red[g * DNF + q * 4 + 2] = acc.z;
    s_red[g * DNF + q * 4 + 3] = acc.w;
    __syncthreads();
    if (tid < 128) {
        float s = 0.f;
#pragma unroll
        for (int gg = 0; gg < 8; gg++) s += s_red[gg * DNF + tid];
        g_er[(size_t)i * DNF + tid] = s;
    }
}

// ---------------------------------------------------------------------------
// GEMM: C[M, N] = sum_p A_p[M,128] @ W[:, p*128 : p*128+128]^T
// W row-major [N, ldw]. 128 threads. Micro-tile: MR=BM/8 rows x 4 cols,
// row-pairs packed as f32x2. BK = 128 (whole K per part).
// Grid: (N/BN, M/BM). No bias, no accumulate.
// ---------------------------------------------------------------------------
template<int BM, int BN>
__global__ void k_gemm(const float* __restrict__ A0,
                       const float* __restrict__ A1,
                       int lda,
                       const float* __restrict__ W, int ldw,
                       float* __restrict__ C, int ldc,
                       int nparts) {
    constexpr int MR = BM / 8;          // 8 (BM=64) or 4 (BM=32)
    constexpr int NPAIR = MR / 2;

    __shared__ __align__(16) float As[128 * BM];
    __shared__ __align__(16) float Ws[128 * BN];

    const int tid = threadIdx.x;        // 128
    const int tx  = tid & 15;           // 16 col groups
    const int ty  = tid >> 4;           // 8 row groups
    const int bm  = blockIdx.y * BM;
    const int bn  = blockIdx.x * BN;
    const int r0  = ty * MR;
    const int c0  = tx * 4;

    unsigned long long acc[NPAIR][4];
#pragma unroll
    for (int rp = 0; rp < NPAIR; rp++)
#pragma unroll
        for (int c = 0; c < 4; c++) acc[rp][c] = 0ull;

    for (int p = 0; p < nparts; ++p) {
        const float* Ap = p ? A1 : A0;
        const float* Wp = W + p * 128;

        // stage A tile (BM x 128), transposed to As[k][m]
#pragma unroll
        for (int u = 0; u < BM / 4; u++) {
            int idx = tid + u * 128;           // over BM*32 float4s
            int row = idx >> 5;
            int kq  = idx & 31;
            float4 v = *(const float4*)(Ap + (size_t)(bm + row) * lda + kq * 4);
            As[(kq * 4 + 0) * BM + row] = v.x;
            As[(kq * 4 + 1) * BM + row] = v.y;
            As[(kq * 4 + 2) * BM + row] = v.z;
            As[(kq * 4 + 3) * BM + row] = v.w;
        }
        // stage W tile (BN x 128), transposed to Ws[k][n]
#pragma unroll
        for (int u = 0; u < BN / 4; u++) {
            int idx = tid + u * 128;
            int wr  = idx >> 5;
            int kq  = idx & 31;
            float4 v = *(const float4*)(Wp + (size_t)(bn + wr) * ldw + kq * 4);
            Ws[(kq * 4 + 0) * BN + wr] = v.x;
            Ws[(kq * 4 + 1) * BN + wr] = v.y;
            Ws[(kq * 4 + 2) * BN + wr] = v.z;
            Ws[(kq * 4 + 3) * BN + wr] = v.w;
        }
        __syncthreads();

#pragma unroll 8
        for (int k = 0; k < 128; ++k) {
            // a row-pairs (f32x2 lanes = 2 consecutive rows)
            unsigned long long ap[NPAIR];
            const ulonglong2* a2 = (const ulonglong2*)(As + k * BM + r0);
#pragma unroll
            for (int qd = 0; qd < MR / 4; qd++) {
                ulonglong2 t = a2[qd];
                ap[qd * 2 + 0] = t.x;
                ap[qd * 2 + 1] = t.y;
            }
            float4 bw = *(const float4*)(Ws + k * BN + c0);
            unsigned long long bd[4];
            bd[0] = dup2(bw.x); bd[1] = dup2(bw.y);
            bd[2] = dup2(bw.z); bd[3] = dup2(bw.w);
#pragma unroll
            for (int rp = 0; rp < NPAIR; rp++)
#pragma unroll
                for (int c = 0; c < 4; c++)
                    fma2(acc[rp][c], ap[rp], bd[c]);
        }
        __syncthreads();
    }

    // write out: each pair holds rows (r0+2rp, r0+2rp+1), cols c0..c0+3
#pragma unroll
    for (int rp = 0; rp < NPAIR; rp++) {
        float lo[4], hi[4];
#pragma unroll
        for (int c = 0; c < 4; c++) unpack2(acc[rp][c], lo[c], hi[c]);
        int row0 = bm + r0 + 2 * rp;
        float4 o0 = make_float4(lo[0], lo[1], lo[2], lo[3]);
        float4 o1 = make_float4(hi[0], hi[1], hi[2], hi[3]);
        *(float4*)(C + (size_t)row0 * ldc + bn + c0)       = o0;
        *(float4*)(C + (size_t)(row0 + 1) * ldc + bn + c0) = o1;
    }
}

// ---------------------------------------------------------------------------
// SpMV: m[i,:] = sum_k nzv[i,k] * hm[nzi[i,k], :] + ce[i,:] + b_msg
// warp per row, float4 per lane over features. hm lives in g_big (ld=512).
// ---------------------------------------------------------------------------
__global__ void k_spmv(const float* __restrict__ b_msg) {
    const int lane = threadIdx.x & 31;
    const int w    = threadIdx.x >> 5;
    const int row  = blockIdx.x * 8 + w;

    const int cnt   = g_nzc[row];
    const int*   ip = g_nzi + (size_t)row * NN;
    const float* vp = g_nzv + (size_t)row * NN;

    float4 acc = make_float4(0.f, 0.f, 0.f, 0.f);
    int k = 0;
    for (; k + 4 <= cnt; k += 4) {
        int   i0 = ip[k], i1 = ip[k+1], i2 = ip[k+2], i3 = ip[k+3];
        float v0 = vp[k], v1 = vp[k+1], v2 = vp[k+2], v3 = vp[k+3];
        float4 h0 = *(const float4*)(g_big + (size_t)i0 * 512 + lane * 4);
        float4 h1 = *(const float4*)(g_big + (size_t)i1 * 512 + lane * 4);
        float4 h2 = *(const float4*)(g_big + (size_t)i2 * 512 + lane * 4);
        float4 h3 = *(const float4*)(g_big + (size_t)i3 * 512 + lane * 4);
        acc.x += v0*h0.x; acc.y += v0*h0.y; acc.z += v0*h0.z; acc.w += v0*h0.w;
        acc.x += v1*h1.x; acc.y += v1*h1.y; acc.z += v1*h1.z; acc.w += v1*h1.w;
        acc.x += v2*h2.x; acc.y += v2*h2.y; acc.z += v2*h2.z; acc.w += v2*h2.w;
        acc.x += v3*h3.x; acc.y += v3*h3.y; acc.z += v3*h3.z; acc.w += v3*h3.w;
    }
    for (; k < cnt; ++k) {
        float v = vp[k];
        float4 hv = *(const float4*)(g_big + (size_t)ip[k] * 512 + lane * 4);
        acc.x += v*hv.x; acc.y += v*hv.y; acc.z += v*hv.z; acc.w += v*hv.w;
    }
    float4 ce = *(const float4*)(g_ce + (size_t)row * DNF + lane * 4);
    float4 bm = *(const float4*)(b_msg + lane * 4);
    float4 o = make_float4(acc.x + ce.x + bm.x, acc.y + ce.y + bm.y,
                           acc.z + ce.z + bm.z, acc.w + ce.w + bm.w);
    *(float4*)(g_m + (size_t)row * DNF + lane * 4) = o;
}

// ---------------------------------------------------------------------------
// GRU elementwise update (biases added here). gh lives in g_big cols 128..511.
// ---------------------------------------------------------------------------
__device__ __forceinline__ float sigmoidf_(float x) { return 1.0f / (1.0f + expf(-x)); }

__global__ void k_gru(const float* __restrict__ h_old,
                      const float* __restrict__ b_ih,
                      const float* __restrict__ b_hh) {
    const int gid = blockIdx.x * blockDim.x + threadIdx.x;  // NN*128
    const int i = gid >> 7;
    const int d = gid & 127;
    const float* gi = g_gi  + (size_t)i * G3;
    const float* gh = g_big + (size_t)i * 512 + 128;
    float r = sigmoidf_(gi[d]       + b_ih[d]       + gh[d]       + b_hh[d]);
    float z = sigmoidf_(gi[128 + d] + b_ih[128 + d] + gh[128 + d] + b_hh[128 + d]);
    float n = tanhf(gi[256 + d] + b_ih[256 + d]
                    + r * (gh[256 + d] + b_hh[256 + d]));
    g_h[gid] = (1.0f - z) * n + z * h_old[gid];
}

// ---------------------------------------------------------------------------
// Readout partials (biases added here). gate_pre at g_gi (ld 128),
// out_pre at g_gi + NN*128 (ld 128).
// ---------------------------------------------------------------------------
__global__ void k_readout_partial(const float* __restrict__ b_gate,
                                  const float* __restrict__ b_out) {
    const int b   = blockIdx.x;     // 64
    const int tid = threadIdx.x;    // 256
    const int d   = tid & 127;
    const int grp = tid >> 7;
    __shared__ float s[256];

    const float* gp0 = g_gi;
    const float* op0 = g_gi + (size_t)NN * DNF;
    const float bg = b_gate[d];
    const float bo = b_out[d];

    const int i0 = b * 16 + grp * 8;
    float acc = 0.0f;
#pragma unroll
    for (int r = 0; r < 8; r++) {
        int i = i0 + r;
        acc += sigmoidf_(gp0[(size_t)i * DNF + d] + bg)
             * tanhf   (op0[(size_t)i * DNF + d] + bo);
    }
    s[tid] = acc;
    __syncthreads();
    if (tid < 128) g_part[b * DNF + tid] = s[tid] + s[tid + 128];
}

// ---------------------------------------------------------------------------
// Final: gv = sum partials; ee = w_embed @ edge; out = w_fc @ [gv,ee] + b_fc
// ---------------------------------------------------------------------------
__global__ void k_final(const float* __restrict__ w_embed,
                        const float* __restrict__ edge,
                        const float* __restrict__ w_fc,
                        const float* __restrict__ b_fc,
                        float* __restrict__ out) {
    const int d = threadIdx.x;   // 128
    __shared__ float s_gv[128];
    __shared__ float s_ee[128];

    float gv = 0.0f;
    for (int b = 0; b < 64; b++) gv += g_part[b * DNF + d];
    s_gv[d] = gv;

    float ee = 0.0f;
#pragma unroll
    for (int f = 0; f < 5; f++) ee += w_embed[d * 5 + f] * edge[f];
    s_ee[d] = ee;
    __syncthreads();

    float acc = b_fc[d];
    const float* wr = w_fc + (size_t)d * 256;
    for (int k = 0; k < 128; k++) acc += wr[k] * s_gv[k];
    for (int k = 0; k < 128; k++) acc += wr[128 + k] * s_ee[k];
    out[d] = acc;
}

// ---------------------------------------------------------------------------
extern "C" void kernel_launch(void* const* d_in, const int* in_sizes, int n_in,
                              void* d_out, int out_size) {
    const float* h_in    = (const float*)d_in[0];
    const float* e       = (const float*)d_in[1];
    const float* adj     = (const float*)d_in[2];
    const float* edge    = (const float*)d_in[3];
    const float* w_msg_h = (const float*)d_in[4];
    const float* w_msg_e = (const float*)d_in[5];
    const float* b_msg   = (const float*)d_in[6];
    const float* w_ih    = (const float*)d_in[7];
    const float* w_hh    = (const float*)d_in[8];
    const float* b_ih    = (const float*)d_in[9];
    const float* b_hh    = (const float*)d_in[10];
    const float* w_gate  = (const float*)d_in[11];
    const float* b_gate  = (const float*)d_in[12];
    const float* w_out   = (const float*)d_in[13];
    const float* b_out   = (const float*)d_in[14];
    const float* w_embed = (const float*)d_in[15];
    const float* w_fc    = (const float*)d_in[16];
    const float* b_fc    = (const float*)d_in[17];
    float* out = (float*)d_out;

    float *p_er, *p_ce, *p_big, *p_m, *p_h, *p_gi, *p_wcat;
    cudaGetSymbolAddress((void**)&p_er,   g_er);
    cudaGetSymbolAddress((void**)&p_ce,   g_ce);
    cudaGetSymbolAddress((void**)&p_big,  g_big);
    cudaGetSymbolAddress((void**)&p_m,    g_m);
    cudaGetSymbolAddress((void**)&p_h,    g_h);
    cudaGetSymbolAddress((void**)&p_gi,   g_gi);
    cudaGetSymbolAddress((void**)&p_wcat, g_wcat);

    // concat [w_msg_h ; w_hh] into g_wcat (512 x 128)
    cudaMemcpyAsync(p_wcat,             w_msg_h, 128 * 128 * sizeof(float),
                    cudaMemcpyDeviceToDevice);
    cudaMemcpyAsync(p_wcat + 128 * 128, w_hh,    384 * 128 * sizeof(float),
                    cudaMemcpyDeviceToDevice);

    // adjacency compaction + e reduction
    k_build_ereduce<<<NN, 256>>>(adj, e);

    // ce = er @ w_msg_e^T
    k_gemm<32, 64><<<dim3(2, 32), 128>>>(p_er, nullptr, 128, w_msg_e, 128,
                                         p_ce, 128, 1);

    // message-passing layers
    for (int l = 0; l < 4; l++) {
        const float* hcur = l ? p_h : h_in;
        // [hm | gh] = h @ [w_msg_h; w_hh]^T   (N=512)
        k_gemm<64, 64><<<dim3(8, 16), 128>>>(hcur, nullptr, 128, p_wcat, 128,
                                             p_big, 512, 1);
        k_spmv<<<128, 256>>>(b_msg);
        // gi = m @ w_ih^T   (N=384)
        k_gemm<64, 64><<<dim3(6, 16), 128>>>(p_m, nullptr, 128, w_ih, 128,
                                             p_gi, G3, 1);
        k_gru<<<(NN * DNF) / 256, 256>>>(hcur, b_ih, b_hh);
    }

    // readout: gate_pre / out_pre over hc = [h_final | h0]  (K=256, 2 parts)
    k_gemm<32, 64><<<dim3(2, 32), 128>>>(p_h, h_in, 128, w_gate, 256,
                                         p_gi, 128, 2);
    k_gemm<32, 64><<<dim3(2, 32), 128>>>(p_h, h_in, 128, w_out, 256,
                                         p_gi + NN * DNF, 128, 2);

    k_readout_partial<<<64, 256>>>(b_gate, b_out);
    k_final<<<1, 128>>>(w_embed, edge, w_fc, b_fc, out);
}

// round 3
// speedup vs baseline: 1.6925x; 1.6925x over previous
#include <cuda_runtime.h>
#include <math.h>

#define NN  1024
#define DNF 128
#define G3  384

#define BM 32
#define BN 64
#define BK 64
#define LDSP 68   // BK + 4 pad (272B: 16B-aligned rows, conflict-free interleave)

// ---------------- device scratch ----------------
__device__ float g_er  [NN * DNF];
__device__ float g_ce  [NN * DNF];
__device__ float g_cei [NN * G3];
__device__ float g_sh  [NN * DNF];     // S . h
__device__ float g_gi  [NN * G3];
__device__ float g_gh  [NN * G3];
__device__ float g_h   [NN * DNF];
__device__ float g_wim [G3 * DNF];     // w_ih @ w_msg_h
__device__ float g_wmhT[DNF * DNF];
__device__ float g_ro  [2 * NN * DNF]; // gate_pre | out_pre
__device__ int   g_nzi [NN * NN];
__device__ float g_nzv [NN * NN];
__device__ int   g_nzc [NN];
__device__ float g_part[64 * DNF];

// ---------------------------------------------------------------------------
// adjacency compaction + adj-weighted reduction of e
// ---------------------------------------------------------------------------
__global__ void k_build_ereduce(const float* __restrict__ adj,
                                const float* __restrict__ e) {
    const int i    = blockIdx.x;
    const int tid  = threadIdx.x;       // 256
    const int lane = tid & 31;
    const int w    = tid >> 5;          // 8 warps

    __shared__ int   s_idx[NN];
    __shared__ float s_val[NN];
    __shared__ int   s_wcnt[8];
    __shared__ int   s_woff[8];
    __shared__ int   s_cnt;
    __shared__ float s_red[8 * DNF];

    const float* arow = adj + (size_t)i * NN;
    const int base = w * 128;

    float av[4]; unsigned mm[4];
#pragma unroll
    for (int c = 0; c < 4; c++) av[c] = arow[base + c * 32 + lane];
    int tot = 0;
#pragma unroll
    for (int c = 0; c < 4; c++) {
        mm[c] = __ballot_sync(0xffffffffu, av[c] != 0.0f);
        tot += __popc(mm[c]);
    }
    if (lane == 0) s_wcnt[w] = tot;
    __syncthreads();
    if (tid == 0) {
        int run = 0;
        for (int ww = 0; ww < 8; ww++) { s_woff[ww] = run; run += s_wcnt[ww]; }
        s_cnt = run;
    }
    __syncthreads();

    int off = s_woff[w];
    const unsigned lm = (1u << lane) - 1u;
#pragma unroll
    for (int c = 0; c < 4; c++) {
        if (av[c] != 0.0f) {
            int p = off + __popc(mm[c] & lm);
            s_idx[p] = base + c * 32 + lane;
            s_val[p] = av[c];
        }
        off += __popc(mm[c]);
    }
    __syncthreads();

    const int cnt = s_cnt;
    if (tid == 0) g_nzc[i] = cnt;
    for (int k = tid; k < cnt; k += 256) {
        g_nzi[(size_t)i * NN + k] = s_idx[k];
        g_nzv[(size_t)i * NN + k] = s_val[k];
    }

    // er[i,:] = sum_k val_k * e[i, idx_k, :]   (8 groups x 32 lanes, float4)
    const int q = tid & 31;
    const int g = tid >> 5;
    const float* ebase = e + (size_t)i * NN * DNF;
    float4 acc = make_float4(0.f, 0.f, 0.f, 0.f);
    for (int k = g; k < cnt; k += 8) {
        float v = s_val[k];
        float4 ev = *(const float4*)(ebase + (size_t)s_idx[k] * DNF + q * 4);
        acc.x += v * ev.x; acc.y += v * ev.y;
        acc.z += v * ev.z; acc.w += v * ev.w;
    }
    s_red[g * DNF + q * 4 + 0] = acc.x;
    s_red[g * DNF + q * 4 + 1] = acc.y;
    s_red[g * DNF + q * 4 + 2] = acc.z;
    s_red[g * DNF + q * 4 + 3] = acc.w;
    __syncthreads();
    if (tid < 128) {
        float s = 0.f;
#pragma unroll
        for (int gg = 0; gg < 8; gg++) s += s_red[gg * DNF + tid];
        g_er[(size_t)i * DNF + tid] = s;
    }
}

// ---------------------------------------------------------------------------
// 128x128 transpose (for w_msg_h)
// ---------------------------------------------------------------------------
__global__ void k_transpose(const float* __restrict__ src,
                            float* __restrict__ dst) {
    __shared__ float t[32][33];
    const int bx = blockIdx.x * 32, by = blockIdx.y * 32;
    const int x = threadIdx.x, y = threadIdx.y;       // (32, 8)
#pragma unroll
    for (int i = 0; i < 32; i += 8)
        t[y + i][x] = src[(size_t)(by + y + i) * DNF + bx + x];
    __syncthreads();
#pragma unroll
    for (int i = 0; i < 32; i += 8)
        dst[(size_t)(bx + y + i) * DNF + by + x] = t[x][y + i];
}

// ---------------------------------------------------------------------------
// Batched GEMM: C = sum_p A_p @ W[:, p*128:(p+1)*128]^T (+bias) (+D)
// A_p row-major [M, lda] (K=128 per part), W row-major [N, ldw].
// BM=32, BN=64, BK=64, 256 threads, 2x4 thread tile (cols interleaved tx+16j).
// blockIdx.z selects arg set (batch of 2 independent GEMMs per launch).
// ---------------------------------------------------------------------------
struct GArg {
    const float* A0; const float* A1;
    const float* W;
    const float* D;      // optional add source [M, ldc]
    const float* bias;   // optional [N]
    float* C;
    int lda, ldw, ldc, nparts;
};

__global__ void k_gemm(GArg ga, GArg gb) {
    const GArg g = blockIdx.z ? gb : ga;

    __shared__ __align__(16) float As[BM * LDSP];
    __shared__ __align__(16) float Ws[BN * LDSP];

    const int tid = threadIdx.x;     // 256
    const int tx  = tid & 15;
    const int ty  = tid >> 4;        // 16
    const int bm  = blockIdx.y * BM;
    const int bn  = blockIdx.x * BN;

    float acc[2][4];
#pragma unroll
    for (int i = 0; i < 2; i++)
#pragma unroll
        for (int j = 0; j < 4; j++) acc[i][j] = 0.f;

    for (int p = 0; p < g.nparts; ++p) {
        const float* Ap = p ? g.A1 : g.A0;
        const float* Wp = g.W + p * 128;

#pragma unroll
        for (int kt = 0; kt < 2; ++kt) {
            // stage A: 32 rows x 64 k  (512 float4, 2/thread)
#pragma unroll
            for (int u = 0; u < 2; ++u) {
                int idx = tid + u * 256;
                int row = idx >> 4;
                int kq  = idx & 15;
                float4 v = *(const float4*)(Ap + (size_t)(bm + row) * g.lda
                                            + kt * BK + kq * 4);
                *(float4*)(As + row * LDSP + kq * 4) = v;
            }
            // stage W: 64 rows x 64 k  (1024 float4, 4/thread)
#pragma unroll
            for (int u = 0; u < 4; ++u) {
                int idx = tid + u * 256;
                int row = idx >> 4;
                int kq  = idx & 15;
                float4 v = *(const float4*)(Wp + (size_t)(bn + row) * g.ldw
                                            + kt * BK + kq * 4);
                *(float4*)(Ws + row * LDSP + kq * 4) = v;
            }
            __syncthreads();

#pragma unroll 4
            for (int k4 = 0; k4 < BK / 4; ++k4) {
                float4 a0 = *(const float4*)(As + (ty * 2 + 0) * LDSP + k4 * 4);
                float4 a1 = *(const float4*)(As + (ty * 2 + 1) * LDSP + k4 * 4);
                float4 b[4];
#pragma unroll
                for (int j = 0; j < 4; ++j)
                    b[j] = *(const float4*)(Ws + (tx + 16 * j) * LDSP + k4 * 4);
#pragma unroll
                for (int j = 0; j < 4; ++j) {
                    acc[0][j] += a0.x * b[j].x; acc[0][j] += a0.y * b[j].y;
                    acc[0][j] += a0.z * b[j].z; acc[0][j] += a0.w * b[j].w;
                    acc[1][j] += a1.x * b[j].x; acc[1][j] += a1.y * b[j].y;
                    acc[1][j] += a1.z * b[j].z; acc[1][j] += a1.w * b[j].w;
                }
            }
            __syncthreads();
        }
    }

#pragma unroll
    for (int i = 0; i < 2; ++i) {
        int row = bm + ty * 2 + i;
#pragma unroll
        for (int j = 0; j < 4; ++j) {
            int col = bn + tx + 16 * j;
            float v = acc[i][j];
            if (g.bias) v += g.bias[col];
            if (g.D)    v += g.D[(size_t)row * g.ldc + col];
            g.C[(size_t)row * g.ldc + col] = v;
        }
    }
}

// ---------------------------------------------------------------------------
// SpMV: sh[i,:] = sum_k nzv[i,k] * h[nzi[i,k], :]     (block per row)
// ---------------------------------------------------------------------------
__global__ void k_spmv(const float* __restrict__ hsrc) {
    const int i   = blockIdx.x;
    const int tid = threadIdx.x;     // 256
    const int q   = tid & 31;        // float4 lane over 128 features
    const int grp = tid >> 5;        // 8 groups
    __shared__ float4 s_red[8][32];

    const int cnt   = g_nzc[i];
    const int*   ip = g_nzi + (size_t)i * NN;
    const float* vp = g_nzv + (size_t)i * NN;

    float4 acc = make_float4(0.f, 0.f, 0.f, 0.f);
    for (int k = grp; k < cnt; k += 8) {
        float v = vp[k];
        float4 hv = *(const float4*)(hsrc + (size_t)ip[k] * DNF + q * 4);
        acc.x += v * hv.x; acc.y += v * hv.y;
        acc.z += v * hv.z; acc.w += v * hv.w;
    }
    s_red[grp][q] = acc;
    __syncthreads();
    if (tid < 32) {
        float4 s = s_red[0][tid];
#pragma unroll
        for (int gg = 1; gg < 8; gg++) {
            float4 t = s_red[gg][tid];
            s.x += t.x; s.y += t.y; s.z += t.z; s.w += t.w;
        }
        *(float4*)(g_sh + (size_t)i * DNF + tid * 4) = s;
    }
}

// ---------------------------------------------------------------------------
// GRU elementwise update
// ---------------------------------------------------------------------------
__device__ __forceinline__ float sigmoidf_(float x) { return 1.0f / (1.0f + expf(-x)); }

__global__ void k_gru(const float* __restrict__ h_old,
                      const float* __restrict__ b_ih,
                      const float* __restrict__ b_hh) {
    const int gid = blockIdx.x * blockDim.x + threadIdx.x;   // NN*128
    const int i = gid >> 7;
    const int d = gid & 127;
    const float* gi = g_gi + (size_t)i * G3;
    const float* gh = g_gh + (size_t)i * G3;
    float r = sigmoidf_(gi[d]       + b_ih[d]       + gh[d]       + b_hh[d]);
    float z = sigmoidf_(gi[128 + d] + b_ih[128 + d] + gh[128 + d] + b_hh[128 + d]);
    float n = tanhf(gi[256 + d] + b_ih[256 + d]
                    + r * (gh[256 + d] + b_hh[256 + d]));
    g_h[gid] = (1.0f - z) * n + z * h_old[gid];
}

// ---------------------------------------------------------------------------
// Readout partials: part[b,:] = sum over 16 rows of sigmoid(gate)*tanh(out)
// ---------------------------------------------------------------------------
__global__ void k_readout_partial() {
    const int b   = blockIdx.x;      // 64
    const int tid = threadIdx.x;     // 256
    const int d   = tid & 127;
    const int grp = tid >> 7;
    __shared__ float s[256];

    const float* gp = g_ro;
    const float* op = g_ro + (size_t)NN * DNF;

    const int i0 = b * 16 + grp * 8;
    float acc = 0.0f;
#pragma unroll
    for (int r = 0; r < 8; r++) {
        int i = i0 + r;
        acc += sigmoidf_(gp[(size_t)i * DNF + d]) * tanhf(op[(size_t)i * DNF + d]);
    }
    s[tid] = acc;
    __syncthreads();
    if (tid < 128) g_part[b * DNF + tid] = s[tid] + s[tid + 128];
}

// ---------------------------------------------------------------------------
// Final: gv = sum partials; ee = w_embed @ edge; out = w_fc @ [gv,ee] + b_fc
// ---------------------------------------------------------------------------
__global__ void k_final(const float* __restrict__ w_embed,
                        const float* __restrict__ edge,
                        const float* __restrict__ w_fc,
                        const float* __restrict__ b_fc,
                        float* __restrict__ out) {
    const int d = threadIdx.x;   // 128
    __shared__ float s_gv[128];
    __shared__ float s_ee[128];

    float gv = 0.0f;
    for (int b = 0; b < 64; b++) gv += g_part[b * DNF + d];
    s_gv[d] = gv;

    float ee = 0.0f;
#pragma unroll
    for (int f = 0; f < 5; f++) ee += w_embed[d * 5 + f] * edge[f];
    s_ee[d] = ee;
    __syncthreads();

    float acc = b_fc[d];
    const float* wr = w_fc + (size_t)d * 256;
    for (int k = 0; k < 128; k++) acc += wr[k] * s_gv[k];
    for (int k = 0; k < 128; k++) acc += wr[128 + k] * s_ee[k];
    out[d] = acc;
}

// ---------------------------------------------------------------------------
extern "C" void kernel_launch(void* const* d_in, const int* in_sizes, int n_in,
                              void* d_out, int out_size) {
    const float* h_in    = (const float*)d_in[0];
    const float* e       = (const float*)d_in[1];
    const float* adj     = (const float*)d_in[2];
    const float* edge    = (const float*)d_in[3];
    const float* w_msg_h = (const float*)d_in[4];
    const float* w_msg_e = (const float*)d_in[5];
    const float* b_msg   = (const float*)d_in[6];
    const float* w_ih    = (const float*)d_in[7];
    const float* w_hh    = (const float*)d_in[8];
    const float* b_ih    = (const float*)d_in[9];
    const float* b_hh    = (const float*)d_in[10];
    const float* w_gate  = (const float*)d_in[11];
    const float* b_gate  = (const float*)d_in[12];
    const float* w_out   = (const float*)d_in[13];
    const float* b_out   = (const float*)d_in[14];
    const float* w_embed = (const float*)d_in[15];
    const float* w_fc    = (const float*)d_in[16];
    const float* b_fc    = (const float*)d_in[17];
    float* out = (float*)d_out;

    float *p_er, *p_ce, *p_cei, *p_sh, *p_gi, *p_gh, *p_h, *p_wim, *p_wmhT, *p_ro;
    cudaGetSymbolAddress((void**)&p_er,   g_er);
    cudaGetSymbolAddress((void**)&p_ce,   g_ce);
    cudaGetSymbolAddress((void**)&p_cei,  g_cei);
    cudaGetSymbolAddress((void**)&p_sh,   g_sh);
    cudaGetSymbolAddress((void**)&p_gi,   g_gi);
    cudaGetSymbolAddress((void**)&p_gh,   g_gh);
    cudaGetSymbolAddress((void**)&p_h,    g_h);
    cudaGetSymbolAddress((void**)&p_wim,  g_wim);
    cudaGetSymbolAddress((void**)&p_wmhT, g_wmhT);
    cudaGetSymbolAddress((void**)&p_ro,   g_ro);

    // setup: transpose + adjacency build
    k_transpose<<<dim3(4, 4), dim3(32, 8)>>>(w_msg_h, p_wmhT);
    k_build_ereduce<<<NN, 256>>>(adj, e);

    // wim = w_ih @ w_msg_h   (M=384, N=128)
    {
        GArg a = { w_ih, nullptr, p_wmhT, nullptr, nullptr, p_wim, 128, 128, 128, 1 };
        k_gemm<<<dim3(DNF / BN, G3 / BM, 1), 256>>>(a, a);
    }
    // ce = er @ w_msg_e^T + b_msg   (N=128)
    {
        GArg a = { p_er, nullptr, w_msg_e, nullptr, b_msg, p_ce, 128, 128, 128, 1 };
        k_gemm<<<dim3(DNF / BN, NN / BM, 1), 256>>>(a, a);
    }
    // cei = ce @ w_ih^T   (N=384)
    {
        GArg a = { p_ce, nullptr, w_ih, nullptr, nullptr, p_cei, 128, 128, G3, 1 };
        k_gemm<<<dim3(G3 / BN, NN / BM, 1), 256>>>(a, a);
    }

    // message-passing layers
    for (int l = 0; l < 4; l++) {
        const float* hcur = l ? p_h : h_in;
        k_spmv<<<NN, 256>>>(hcur);
        // z=0: gi = sh @ wim^T + cei ;  z=1: gh = h @ w_hh^T
        GArg agi = { p_sh, nullptr, p_wim, p_cei, nullptr, p_gi, 128, 128, G3, 1 };
        GArg agh = { hcur, nullptr, w_hh,  nullptr, nullptr, p_gh, 128, 128, G3, 1 };
        k_gemm<<<dim3(G3 / BN, NN / BM, 2), 256>>>(agi, agh);
        k_gru<<<(NN * DNF) / 256, 256>>>(hcur, b_ih, b_hh);
    }

    // readout: gate_pre / out_pre over hc = [h_final | h0]  (K=256, 2 parts)
    {
        GArg ag = { p_h, h_in, w_gate, nullptr, b_gate, p_ro,            128, 256, 128, 2 };
        GArg ao = { p_h, h_in, w_out,  nullptr, b_out,  p_ro + NN * DNF, 128, 256, 128, 2 };
        k_gemm<<<dim3(DNF / BN, NN / BM, 2), 256>>>(ag, ao);
    }

    k_readout_partial<<<64, 256>>>();
    k_final<<<1, 128>>>(w_embed, edge, w_fc, b_fc, out);
}

// round 4
// speedup vs baseline: 1.8570x; 1.0972x over previous
#include <cuda_runtime.h>
#include <math.h>

#define NN  1024
#define DNF 128
#define G3  384

// GEMM tile params
#define TBM 64
#define TBN 64
#define TBK 64
#define TLD 68    // smem row stride (floats), pad for conflict-free frag loads

// ---------------- device scratch ----------------
__device__ float g_er  [NN * DNF];
__device__ float g_cei [NN * G3];
__device__ float g_sh  [NN * DNF];      // S . h
__device__ float g_gi  [NN * G3];
__device__ float g_gh  [NN * G3];
__device__ float g_h   [NN * DNF];
__device__ float g_wim [G3 * DNF];      // w_ih @ w_msg_h
__device__ float g_wie [G3 * DNF];      // w_ih @ w_msg_e
__device__ float g_wmhT[DNF * DNF];
__device__ float g_wmeT[DNF * DNF];
__device__ float g_bvec[G3];            // w_ih @ b_msg
__device__ float g_ro  [2 * NN * DNF];  // gate_pre | out_pre
__device__ int   g_nzi [NN * NN];
__device__ float g_nzv [NN * NN];
__device__ int   g_nzc [NN];
__device__ float g_part[64 * DNF];

// ---------------------------------------------------------------------------
// prep: z=0 transpose w_msg_h, z=1 transpose w_msg_e, z=2 bvec = w_ih @ b_msg
// ---------------------------------------------------------------------------
__global__ void k_prep(const float* __restrict__ w_msg_h,
                       const float* __restrict__ w_msg_e,
                       const float* __restrict__ w_ih,
                       const float* __restrict__ b_msg) {
    if (blockIdx.z < 2) {
        __shared__ float t[32][33];
        const float* src = blockIdx.z ? w_msg_e : w_msg_h;
        float* dst = blockIdx.z ? g_wmeT : g_wmhT;
        const int bx = blockIdx.x * 32, by = blockIdx.y * 32;
        const int x = threadIdx.x, y = threadIdx.y;    // (32, 8)
#pragma unroll
        for (int i = 0; i < 32; i += 8)
            t[y + i][x] = src[(size_t)(by + y + i) * DNF + bx + x];
        __syncthreads();
#pragma unroll
        for (int i = 0; i < 32; i += 8)
            dst[(size_t)(bx + y + i) * DNF + by + x] = t[x][y + i];
    } else {
        if (blockIdx.x || blockIdx.y) return;
        __shared__ float sb[DNF];
        const int tid = threadIdx.y * 32 + threadIdx.x;   // 256
        if (tid < DNF) sb[tid] = b_msg[tid];
        __syncthreads();
        for (int n = tid; n < G3; n += 256) {
            float acc = 0.f;
            const float* wr = w_ih + (size_t)n * DNF;
            for (int k = 0; k < DNF; k++) acc += wr[k] * sb[k];
            g_bvec[n] = acc;
        }
    }
}

// ---------------------------------------------------------------------------
// adjacency compaction + adj-weighted reduction of e
// ---------------------------------------------------------------------------
__global__ void k_build_ereduce(const float* __restrict__ adj,
                                const float* __restrict__ e) {
    const int i    = blockIdx.x;
    const int tid  = threadIdx.x;       // 256
    const int lane = tid & 31;
    const int w    = tid >> 5;          // 8 warps

    __shared__ int   s_idx[NN];
    __shared__ float s_val[NN];
    __shared__ int   s_wcnt[8];
    __shared__ int   s_woff[8];
    __shared__ int   s_cnt;
    __shared__ float s_red[8 * DNF];

    const float* arow = adj + (size_t)i * NN;
    const int base = w * 128;

    float av[4]; unsigned mm[4];
#pragma unroll
    for (int c = 0; c < 4; c++) av[c] = arow[base + c * 32 + lane];
    int tot = 0;
#pragma unroll
    for (int c = 0; c < 4; c++) {
        mm[c] = __ballot_sync(0xffffffffu, av[c] != 0.0f);
        tot += __popc(mm[c]);
    }
    if (lane == 0) s_wcnt[w] = tot;
    __syncthreads();
    if (tid == 0) {
        int run = 0;
        for (int ww = 0; ww < 8; ww++) { s_woff[ww] = run; run += s_wcnt[ww]; }
        s_cnt = run;
    }
    __syncthreads();

    int off = s_woff[w];
    const unsigned lm = (1u << lane) - 1u;
#pragma unroll
    for (int c = 0; c < 4; c++) {
        if (av[c] != 0.0f) {
            int p = off + __popc(mm[c] & lm);
            s_idx[p] = base + c * 32 + lane;
            s_val[p] = av[c];
        }
        off += __popc(mm[c]);
    }
    __syncthreads();

    const int cnt = s_cnt;
    if (tid == 0) g_nzc[i] = cnt;
    for (int k = tid; k < cnt; k += 256) {
        g_nzi[(size_t)i * NN + k] = s_idx[k];
        g_nzv[(size_t)i * NN + k] = s_val[k];
    }

    // er[i,:] = sum_k val_k * e[i, idx_k, :]
    const int q = tid & 31;
    const int g = tid >> 5;
    const float* ebase = e + (size_t)i * NN * DNF;
    float4 acc = make_float4(0.f, 0.f, 0.f, 0.f);
    for (int k = g; k < cnt; k += 8) {
        float v = s_val[k];
        float4 ev = *(const float4*)(ebase + (size_t)s_idx[k] * DNF + q * 4);
        acc.x += v * ev.x; acc.y += v * ev.y;
        acc.z += v * ev.z; acc.w += v * ev.w;
    }
    s_red[g * DNF + q * 4 + 0] = acc.x;
    s_red[g * DNF + q * 4 + 1] = acc.y;
    s_red[g * DNF + q * 4 + 2] = acc.z;
    s_red[g * DNF + q * 4 + 3] = acc.w;
    __syncthreads();
    if (tid < 128) {
        float s = 0.f;
#pragma unroll
        for (int gg = 0; gg < 8; gg++) s += s_red[gg * DNF + tid];
        g_er[(size_t)i * DNF + tid] = s;
    }
}

// ---------------------------------------------------------------------------
// TF32 tensor-core GEMM:  C[M,N] = sum_p A_p[M,128] @ W[:, p*128:+128]^T
//                                   (+ bias[N]) (+ D[M,N])
// 128 threads (2x2 warps), block tile 64x64, BK=64.
// mma.sync.m16n8k8.row.col.f32.tf32.tf32.f32
// blockIdx.z selects arg set.
// ---------------------------------------------------------------------------
struct GArg {
    const float* A0; const float* A1;
    const float* W;
    const float* D;
    const float* bias;
    float* C;
    int lda, ldw, ldc, nparts;
};

__device__ __forceinline__ float to_tf32(float x) {
    float r;
    asm("cvt.rna.tf32.f32 %0, %1;" : "=f"(r) : "f"(x));
    return r;
}

__global__ void __launch_bounds__(128) k_gemm_tc(GArg ga, GArg gb) {
    const GArg g = blockIdx.z ? gb : ga;

    __shared__ __align__(16) float As[TBM * TLD];
    __shared__ __align__(16) float Ws[TBN * TLD];

    const int tid  = threadIdx.x;       // 128
    const int lane = tid & 31;
    const int wrp  = tid >> 5;          // 4 warps
    const int wm   = wrp >> 1;          // 0..1
    const int wn   = wrp & 1;           // 0..1
    const int q    = lane >> 2;         // 0..7
    const int r    = lane & 3;          // 0..3
    const int bm   = blockIdx.y * TBM;
    const int bn   = blockIdx.x * TBN;

    float acc[2][4][4];
#pragma unroll
    for (int s = 0; s < 2; s++)
#pragma unroll
        for (int j = 0; j < 4; j++)
#pragma unroll
            for (int c = 0; c < 4; c++) acc[s][j][c] = 0.f;

    for (int p = 0; p < g.nparts; ++p) {
        const float* Ap = p ? g.A1 : g.A0;
        const float* Wp = g.W + p * 128;

#pragma unroll
        for (int kt = 0; kt < 2; ++kt) {
            // stage A tile 64 rows x 64 k  (1024 float4, 8/thread)
#pragma unroll
            for (int u = 0; u < 8; ++u) {
                int idx = tid + u * 128;
                int row = idx >> 4;
                int kq  = idx & 15;
                float4 v = *(const float4*)(Ap + (size_t)(bm + row) * g.lda
                                            + kt * TBK + kq * 4);
                float* d = As + row * TLD + kq * 4;
                d[0] = to_tf32(v.x); d[1] = to_tf32(v.y);
                d[2] = to_tf32(v.z); d[3] = to_tf32(v.w);
            }
            // stage W tile 64 rows(n) x 64 k
#pragma unroll
            for (int u = 0; u < 8; ++u) {
                int idx = tid + u * 128;
                int row = idx >> 4;
                int kq  = idx & 15;
                float4 v = *(const float4*)(Wp + (size_t)(bn + row) * g.ldw
                                            + kt * TBK + kq * 4);
                float* d = Ws + row * TLD + kq * 4;
                d[0] = to_tf32(v.x); d[1] = to_tf32(v.y);
                d[2] = to_tf32(v.z); d[3] = to_tf32(v.w);
            }
            __syncthreads();

#pragma unroll
            for (int k8 = 0; k8 < TBK / 8; ++k8) {
                const int ko = k8 * 8;
                // A fragments: 2 m16 subtiles
                unsigned a[2][4];
#pragma unroll
                for (int s = 0; s < 2; s++) {
                    int ar = wm * 32 + s * 16 + q;
                    a[s][0] = __float_as_uint(As[(ar    ) * TLD + ko + r    ]);
                    a[s][1] = __float_as_uint(As[(ar + 8) * TLD + ko + r    ]);
                    a[s][2] = __float_as_uint(As[(ar    ) * TLD + ko + r + 4]);
                    a[s][3] = __float_as_uint(As[(ar + 8) * TLD + ko + r + 4]);
                }
                // B fragments: 4 n8 subtiles
                unsigned b[4][2];
#pragma unroll
                for (int j = 0; j < 4; j++) {
                    int nrow = wn * 32 + j * 8 + q;
                    b[j][0] = __float_as_uint(Ws[nrow * TLD + ko + r    ]);
                    b[j][1] = __float_as_uint(Ws[nrow * TLD + ko + r + 4]);
                }
#pragma unroll
                for (int s = 0; s < 2; s++)
#pragma unroll
                    for (int j = 0; j < 4; j++) {
                        asm volatile(
                            "mma.sync.aligned.m16n8k8.row.col.f32.tf32.tf32.f32 "
                            "{%0,%1,%2,%3}, {%4,%5,%6,%7}, {%8,%9}, {%0,%1,%2,%3};"
                            : "+f"(acc[s][j][0]), "+f"(acc[s][j][1]),
                              "+f"(acc[s][j][2]), "+f"(acc[s][j][3])
                            : "r"(a[s][0]), "r"(a[s][1]), "r"(a[s][2]), "r"(a[s][3]),
                              "r"(b[j][0]), "r"(b[j][1]));
                    }
            }
            __syncthreads();
        }
    }

    // epilogue
#pragma unroll
    for (int s = 0; s < 2; s++) {
        int row0 = bm + wm * 32 + s * 16 + q;
#pragma unroll
        for (int j = 0; j < 4; j++) {
            int col = bn + wn * 32 + j * 8 + 2 * r;
            float v0 = acc[s][j][0], v1 = acc[s][j][1];
            float v2 = acc[s][j][2], v3 = acc[s][j][3];
            if (g.bias) {
                float b0 = g.bias[col], b1 = g.bias[col + 1];
                v0 += b0; v1 += b1; v2 += b0; v3 += b1;
            }
            if (g.D) {
                const float* d0 = g.D + (size_t)row0 * g.ldc + col;
                const float* d1 = g.D + (size_t)(row0 + 8) * g.ldc + col;
                v0 += d0[0]; v1 += d0[1]; v2 += d1[0]; v3 += d1[1];
            }
            *(float2*)(g.C + (size_t)row0 * g.ldc + col)       = make_float2(v0, v1);
            *(float2*)(g.C + (size_t)(row0 + 8) * g.ldc + col) = make_float2(v2, v3);
        }
    }
}

// ---------------------------------------------------------------------------
// SpMV: sh[i,:] = sum_k nzv[i,k] * h[nzi[i,k], :]
// ---------------------------------------------------------------------------
__global__ void k_spmv(const float* __restrict__ hsrc) {
    const int i   = blockIdx.x;
    const int tid = threadIdx.x;     // 256
    const int q   = tid & 31;
    const int grp = tid >> 5;
    __shared__ float4 s_red[8][32];

    const int cnt   = g_nzc[i];
    const int*   ip = g_nzi + (size_t)i * NN;
    const float* vp = g_nzv + (size_t)i * NN;

    float4 acc = make_float4(0.f, 0.f, 0.f, 0.f);
    for (int k = grp; k < cnt; k += 8) {
        float v = vp[k];
        float4 hv = *(const float4*)(hsrc + (size_t)ip[k] * DNF + q * 4);
        acc.x += v * hv.x; acc.y += v * hv.y;
        acc.z += v * hv.z; acc.w += v * hv.w;
    }
    s_red[grp][q] = acc;
    __syncthreads();
    if (tid < 32) {
        float4 s = s_red[0][tid];
#pragma unroll
        for (int gg = 1; gg < 8; gg++) {
            float4 t = s_red[gg][tid];
            s.x += t.x; s.y += t.y; s.z += t.z; s.w += t.w;
        }
        *(float4*)(g_sh + (size_t)i * DNF + tid * 4) = s;
    }
}

// ---------------------------------------------------------------------------
// GRU elementwise update
// ---------------------------------------------------------------------------
__device__ __forceinline__ float sigmoidf_(float x) { return 1.0f / (1.0f + expf(-x)); }

__global__ void k_gru(const float* __restrict__ h_old,
                      const float* __restrict__ b_ih,
                      const float* __restrict__ b_hh) {
    const int gid = blockIdx.x * blockDim.x + threadIdx.x;   // NN*128
    const int i = gid >> 7;
    const int d = gid & 127;
    const float* gi = g_gi + (size_t)i * G3;
    const float* gh = g_gh + (size_t)i * G3;
    float r = sigmoidf_(gi[d]       + b_ih[d]       + gh[d]       + b_hh[d]);
    float z = sigmoidf_(gi[128 + d] + b_ih[128 + d] + gh[128 + d] + b_hh[128 + d]);
    float n = tanhf(gi[256 + d] + b_ih[256 + d]
                    + r * (gh[256 + d] + b_hh[256 + d]));
    g_h[gid] = (1.0f - z) * n + z * h_old[gid];
}

// ---------------------------------------------------------------------------
// Readout partials
// ---------------------------------------------------------------------------
__global__ void k_readout_partial() {
    const int b   = blockIdx.x;      // 64
    const int tid = threadIdx.x;     // 256
    const int d   = tid & 127;
    const int grp = tid >> 7;
    __shared__ float s[256];

    const float* gp = g_ro;
    const float* op = g_ro + (size_t)NN * DNF;

    const int i0 = b * 16 + grp * 8;
    float acc = 0.0f;
#pragma unroll
    for (int rr = 0; rr < 8; rr++) {
        int i = i0 + rr;
        acc += sigmoidf_(gp[(size_t)i * DNF + d]) * tanhf(op[(size_t)i * DNF + d]);
    }
    s[tid] = acc;
    __syncthreads();
    if (tid < 128) g_part[b * DNF + tid] = s[tid] + s[tid + 128];
}

// ---------------------------------------------------------------------------
// Final
// ---------------------------------------------------------------------------
__global__ void k_final(const float* __restrict__ w_embed,
                        const float* __restrict__ edge,
                        const float* __restrict__ w_fc,
                        const float* __restrict__ b_fc,
                        float* __restrict__ out) {
    const int d = threadIdx.x;   // 128
    __shared__ float s_gv[128];
    __shared__ float s_ee[128];

    float gv = 0.0f;
    for (int b = 0; b < 64; b++) gv += g_part[b * DNF + d];
    s_gv[d] = gv;

    float ee = 0.0f;
#pragma unroll
    for (int f = 0; f < 5; f++) ee += w_embed[d * 5 + f] * edge[f];
    s_ee[d] = ee;
    __syncthreads();

    float acc = b_fc[d];
    const float* wr = w_fc + (size_t)d * 256;
    for (int k = 0; k < 128; k++) acc += wr[k] * s_gv[k];
    for (int k = 0; k < 128; k++) acc += wr[128 + k] * s_ee[k];
    out[d] = acc;
}

// ---------------------------------------------------------------------------
extern "C" void kernel_launch(void* const* d_in, const int* in_sizes, int n_in,
                              void* d_out, int out_size) {
    const float* h_in    = (const float*)d_in[0];
    const float* e       = (const float*)d_in[1];
    const float* adj     = (const float*)d_in[2];
    const float* edge    = (const float*)d_in[3];
    const float* w_msg_h = (const float*)d_in[4];
    const float* w_msg_e = (const float*)d_in[5];
    const float* b_msg   = (const float*)d_in[6];
    const float* w_ih    = (const float*)d_in[7];
    const float* w_hh    = (const float*)d_in[8];
    const float* b_ih    = (const float*)d_in[9];
    const float* b_hh    = (const float*)d_in[10];
    const float* w_gate  = (const float*)d_in[11];
    const float* b_gate  = (const float*)d_in[12];
    const float* w_out   = (const float*)d_in[13];
    const float* b_out   = (const float*)d_in[14];
    const float* w_embed = (const float*)d_in[15];
    const float* w_fc    = (const float*)d_in[16];
    const float* b_fc    = (const float*)d_in[17];
    float* out = (float*)d_out;

    float *p_er, *p_cei, *p_sh, *p_gi, *p_gh, *p_h;
    float *p_wim, *p_wie, *p_wmhT, *p_wmeT, *p_bvec, *p_ro;
    cudaGetSymbolAddress((void**)&p_er,   g_er);
    cudaGetSymbolAddress((void**)&p_cei,  g_cei);
    cudaGetSymbolAddress((void**)&p_sh,   g_sh);
    cudaGetSymbolAddress((void**)&p_gi,   g_gi);
    cudaGetSymbolAddress((void**)&p_gh,   g_gh);
    cudaGetSymbolAddress((void**)&p_h,    g_h);
    cudaGetSymbolAddress((void**)&p_wim,  g_wim);
    cudaGetSymbolAddress((void**)&p_wie,  g_wie);
    cudaGetSymbolAddress((void**)&p_wmhT, g_wmhT);
    cudaGetSymbolAddress((void**)&p_wmeT, g_wmeT);
    cudaGetSymbolAddress((void**)&p_bvec, g_bvec);
    cudaGetSymbolAddress((void**)&p_ro,   g_ro);

    // prep: transposes (z=0,1) + bvec (z=2)
    k_prep<<<dim3(4, 4, 3), dim3(32, 8)>>>(w_msg_h, w_msg_e, w_ih, b_msg);
    // adjacency compaction + e reduction
    k_build_ereduce<<<NN, 256>>>(adj, e);

    // wim = w_ih @ w_msg_h ; wie = w_ih @ w_msg_e   (M=384, N=128)
    {
        GArg a = { w_ih, nullptr, p_wmhT, nullptr, nullptr, p_wim, 128, 128, 128, 1 };
        GArg b = { w_ih, nullptr, p_wmeT, nullptr, nullptr, p_wie, 128, 128, 128, 1 };
        k_gemm_tc<<<dim3(DNF / TBN, G3 / TBM, 2), 128>>>(a, b);
    }
    // cei = er @ wie^T + bvec   (M=1024, N=384)
    {
        GArg a = { p_er, nullptr, p_wie, nullptr, p_bvec, p_cei, 128, 128, G3, 1 };
        k_gemm_tc<<<dim3(G3 / TBN, NN / TBM, 1), 128>>>(a, a);
    }

    // message-passing layers
    for (int l = 0; l < 4; l++) {
        const float* hcur = l ? p_h : h_in;
        k_spmv<<<NN, 256>>>(hcur);
        GArg agi = { p_sh, nullptr, p_wim, p_cei, nullptr, p_gi, 128, 128, G3, 1 };
        GArg agh = { hcur, nullptr, w_hh,  nullptr, nullptr, p_gh, 128, 128, G3, 1 };
        k_gemm_tc<<<dim3(G3 / TBN, NN / TBM, 2), 128>>>(agi, agh);
        k_gru<<<(NN * DNF) / 256, 256>>>(hcur, b_ih, b_hh);
    }

    // readout: K=256 over [h_final | h0]
    {
        GArg ag = { p_h, h_in, w_gate, nullptr, b_gate, p_ro,            128, 256, 128, 2 };
        GArg ao = { p_h, h_in, w_out,  nullptr, b_out,  p_ro + NN * DNF, 128, 256, 128, 2 };
        k_gemm_tc<<<dim3(DNF / TBN, NN / TBM, 2), 128>>>(ag, ao);
    }

    k_readout_partial<<<64, 256>>>();
    k_final<<<1, 128>>>(w_embed, edge, w_fc, b_fc, out);
}